// round 11
// baseline (speedup 1.0000x reference)
#include <cuda_runtime.h>
#include <cstdint>

// Problem constants
#define NPTS   32768            // 32 * 32 * 32 points
#define DIM    64               // embedding dim
#define NE     1024             // codebook size
#define HW     1024             // 32*32 spatial
#define BHW    65536            // 64 channels * 1024 hw (per-batch stride in z)
#define PTSB   64               // points per block
#define CCH    64               // codes per chunk
#define NCH    16               // chunks
#define NBLK   (NPTS / PTSB)    // 512 blocks

// Output layout (flat concat of reference return tuple, float32):
// loss[1], z_q[2097152], perplexity[1], min_encodings[33554432], indices[32768]
#define OFF_LOSS 0ULL
#define OFF_ZQ   1ULL
#define OFF_PERP 2097153ULL
#define OFF_ENC  2097154ULL
#define OFF_IDX  35651586ULL

__device__ float        d_esq[NE];
__device__ float        d_est[DIM * NE];   // transposed codebook [k][c]
__device__ unsigned int d_count[NE];
__device__ float        d_loss = 0.f;
__device__ unsigned int d_done = 0u;

// ---------------------------------------------------------------- helpers
struct __align__(16) ull2 { unsigned long long a, b; };

static __device__ __forceinline__ unsigned long long pk2(float v) {
    unsigned long long r;
    asm("mov.b64 %0, {%1,%2};" : "=l"(r) : "f"(v), "f"(v));
    return r;
}
static __device__ __forceinline__ void ffma2(unsigned long long& d,
                                             unsigned long long a,
                                             unsigned long long b) {
    asm("fma.rn.f32x2 %0, %1, %2, %0;" : "+l"(d) : "l"(a), "l"(b));
}
static __device__ __forceinline__ float2 upk(unsigned long long v) {
    float2 f;
    asm("mov.b64 {%0,%1}, %2;" : "=f"(f.x), "=f"(f.y) : "l"(v));
    return f;
}
static __device__ __forceinline__ unsigned int ordf(float x) {
    unsigned int b = __float_as_uint(x);
    return b ^ (unsigned int)(((int)b >> 31) | 0x80000000);
}
static __device__ __forceinline__ void cpasync16(unsigned int dst_smem,
                                                 const void* src) {
    asm volatile("cp.async.ca.shared.global [%0], [%1], 16;"
                 :: "r"(dst_smem), "l"(src));
}
#define CP_COMMIT() asm volatile("cp.async.commit_group;" ::: "memory")
#define CP_WAIT0()  asm volatile("cp.async.wait_group 0;" ::: "memory")

// ---------------------------------------------------------------- prep
// 16 blocks x 128 threads; block handles 64 codes. Verified ~5.3us.
__global__ void prep_kernel(const float* __restrict__ emb) {
    __shared__ float sb[64][DIM + 1];
    const int tid = threadIdx.x;
    const int c0  = blockIdx.x * 64;

    const float4* src = (const float4*)(emb + (size_t)c0 * DIM);
    #pragma unroll
    for (int i = 0; i < 8; ++i) {
        int f  = i * 128 + tid;
        int c  = f >> 4;
        int k4 = f & 15;
        float4 v = src[f];
        sb[c][k4 * 4 + 0] = v.x;
        sb[c][k4 * 4 + 1] = v.y;
        sb[c][k4 * 4 + 2] = v.z;
        sb[c][k4 * 4 + 3] = v.w;
    }
    __syncthreads();

    if (tid < 64) {
        const int c = c0 + tid;
        float s = 0.f;
        #pragma unroll
        for (int k = 0; k < DIM; ++k) {
            float v = sb[tid][k];
            s = __fadd_rn(s, __fmul_rn(v, v));
            d_est[k * NE + c] = v;
        }
        d_esq[c]   = s;
        d_count[c] = 0u;
        if (c == 0) { d_loss = 0.f; d_done = 0u; }
    }
}

// ---------------------------------------------------------------- main fused kernel
// block: 128 threads = 16 pt-groups (pt_t, 4 pts) x 8 code-groups (cg, 8 codes)
// block tile: 64 points x 64 codes per chunk (16 chunks -> 1024 codes)
// thread tile: 4 points (2 NATURAL f32x2 pairs) x 8 codes (LDS.64 + MOV-dup)
//   per warp-k: 1 LDS.128 z (2 wf) + 4 LDS.64 es (4 wf) vs 16 ffma2 (8 fma-cyc)
//   -> fma-bound. acc[2][8]=32 regs -> fits occ 4.
__global__ void __launch_bounds__(128, 4)
vq_main_kernel(const float* __restrict__ z, const float* __restrict__ emb,
               float* __restrict__ out)
{
    __shared__ __align__(16) float zs[DIM][PTSB];      // [k][pt] 16 KB
    __shared__ __align__(16) float es[2][DIM][CCH];    // [k][c] 2x16 KB
    __shared__ float zsq_s[PTSB];
    __shared__ float warp_s[4];
    __shared__ int   last_s;
    // red overlays es[0] (only used after the last chunk's compute)
    unsigned long long (*red)[PTSB] =
        (unsigned long long (*)[PTSB])&es[0][0][0];    // 8 x 64 x 8B = 4 KB

    const int tid  = threadIdx.x;
    const int pt_t = tid & 15;    // 0..15 point group (4 pts)
    const int cg   = tid >> 4;    // 0..7  code group (8 codes)
    const int pt0  = blockIdx.x * PTSB;
    const int b    = pt0 >> 10;
    const int hw0  = pt0 & 1023;
    const float* zb = z + (size_t)b * BHW + hw0;

    // issue es chunk 0 fetch immediately (16 KB from transposed d_est)
    {
        unsigned int dst0 = (unsigned int)__cvta_generic_to_shared(&es[0][0][0]);
        #pragma unroll
        for (int i = 0; i < 8; ++i) {
            int f = i * 128 + tid;           // 16B unit 0..1023
            int k = f >> 4, c16 = f & 15;    // 16 units per k-row
            cpasync16(dst0 + (unsigned)(k * CCH + c16 * 4) * 4u,
                      &d_est[(size_t)k * NE + c16 * 4]);
        }
        CP_COMMIT();
    }

    // load z tile (coalesced), natural layout [k][pt]
    #pragma unroll
    for (int i = 0; i < 32; ++i) {
        int f = i * 128 + tid;
        int k = f >> 6, p = f & 63;
        zs[k][p] = zb[(size_t)k * HW + p];
    }

    // one-hot region head/tail scalars (base%4==2); float4 body interleaved below
    float* encb = out + OFF_ENC + (size_t)pt0 * NE;    // 65536 floats
    float4* e4  = (float4*)(encb + 2);                 // 16383 float4s
    if (tid == 0) {
        encb[0] = 0.f; encb[1] = 0.f;
        encb[65534] = 0.f; encb[65535] = 0.f;
    }
    __syncthreads();

    // per-point ||z||^2, sequential fp32 rn (matches reference rounding)
    if (tid < PTSB) {
        float s = 0.f;
        #pragma unroll
        for (int k = 0; k < DIM; ++k) {
            float v = zs[k][tid];
            s = __fadd_rn(s, __fmul_rn(v, v));
        }
        zsq_s[tid] = s;
    }

    unsigned long long best[4];
    #pragma unroll
    for (int p = 0; p < 4; ++p) best[p] = 0xFFFFFFFFFFFFFFFFULL;

    for (int h = 0; h < NCH; ++h) {
        const int buf = h & 1;
        CP_WAIT0();            // chunk h landed
        __syncthreads();       // visible to all; h-1 compute done (covers zsq_s)

        // prefetch chunk h+1 into the other buffer (overlaps compute)
        if (h + 1 < NCH) {
            unsigned int dstn = (unsigned int)__cvta_generic_to_shared(
                &es[buf ^ 1][0][0]);
            const float* src = d_est + (size_t)(h + 1) * CCH;
            #pragma unroll
            for (int i = 0; i < 8; ++i) {
                int f = i * 128 + tid;
                int k = f >> 4, c16 = f & 15;
                cpasync16(dstn + (unsigned)(k * CCH + c16 * 4) * 4u,
                          src + (size_t)k * NE + c16 * 4);
            }
        }
        CP_COMMIT();

        // interleaved one-hot zero-fill slice (drains under the FMAs)
        #pragma unroll
        for (int i = 0; i < 8; ++i) {
            int j = h * 1024 + i * 128 + tid;
            if (j < 16383) e4[j] = make_float4(0.f, 0.f, 0.f, 0.f);
        }

        unsigned long long acc[2][8];      // [point-pair][code]
        #pragma unroll
        for (int pp = 0; pp < 2; ++pp)
            #pragma unroll
            for (int j = 0; j < 8; ++j) acc[pp][j] = 0ULL;

        #pragma unroll 4
        for (int k = 0; k < DIM; ++k) {
            ull2 zp = *(const ull2*)&zs[k][pt_t * 4];        // 2 natural pairs
            const ull2* ek = (const ull2*)&es[buf][k][cg * 8];
            ull2 eA = ek[0];   // codes 0,1 of group
            ull2 eB = ek[1];   // codes 2,3
            {
                float2 f0 = upk(eA.a), f1 = upk(eA.b);
                unsigned long long e0 = pk2(f0.x), e1 = pk2(f0.y);
                unsigned long long e2 = pk2(f1.x), e3 = pk2(f1.y);
                ffma2(acc[0][0], zp.a, e0); ffma2(acc[1][0], zp.b, e0);
                ffma2(acc[0][1], zp.a, e1); ffma2(acc[1][1], zp.b, e1);
                ffma2(acc[0][2], zp.a, e2); ffma2(acc[1][2], zp.b, e2);
                ffma2(acc[0][3], zp.a, e3); ffma2(acc[1][3], zp.b, e3);
            }
            {
                float2 f0 = upk(eB.a), f1 = upk(eB.b);
                unsigned long long e4r = pk2(f0.x), e5 = pk2(f0.y);
                unsigned long long e6 = pk2(f1.x), e7 = pk2(f1.y);
                ffma2(acc[0][4], zp.a, e4r); ffma2(acc[1][4], zp.b, e4r);
                ffma2(acc[0][5], zp.a, e5);  ffma2(acc[1][5], zp.b, e5);
                ffma2(acc[0][6], zp.a, e6);  ffma2(acc[1][6], zp.b, e6);
                ffma2(acc[0][7], zp.a, e7);  ffma2(acc[1][7], zp.b, e7);
            }
        }

        // distances + running argmin (u64 key -> first-index tie-break)
        const int cbase = h * CCH + cg * 8;
        #pragma unroll
        for (int j = 0; j < 8; ++j) {
            float esq = __ldg(&d_esq[cbase + j]);
            unsigned code = (unsigned)(cbase + j);
            #pragma unroll
            for (int pp = 0; pp < 2; ++pp) {
                float2 dot = upk(acc[pp][j]);
                {
                    float zq2 = zsq_s[pt_t * 4 + 2 * pp];
                    float d = __fadd_rn(__fadd_rn(zq2, esq), -2.0f * dot.x);
                    unsigned long long k64 =
                        ((unsigned long long)ordf(d) << 32) | code;
                    if (k64 < best[2 * pp]) best[2 * pp] = k64;
                }
                {
                    float zq2 = zsq_s[pt_t * 4 + 2 * pp + 1];
                    float d = __fadd_rn(__fadd_rn(zq2, esq), -2.0f * dot.y);
                    unsigned long long k64 =
                        ((unsigned long long)ordf(d) << 32) | code;
                    if (k64 < best[2 * pp + 1]) best[2 * pp + 1] = k64;
                }
            }
        }
    }

    // cross-thread argmin reduction per point (red overlays es[0])
    __syncthreads();
    #pragma unroll
    for (int p = 0; p < 4; ++p) red[cg][pt_t * 4 + p] = best[p];
    __syncthreads();

    if (tid < PTSB) {
        unsigned long long bk = red[0][tid];
        #pragma unroll
        for (int t = 1; t < 8; ++t) {
            unsigned long long v = red[t][tid];
            if (v < bk) bk = v;
        }
        int idx = (int)(unsigned int)bk;
        int n   = pt0 + tid;

        out[OFF_IDX + n] = (float)idx;
        atomicAdd(&d_count[idx], 1u);
        out[OFF_ENC + (unsigned long long)n * NE + (unsigned)idx] = 1.0f;

        // z_q gather + loss partial (straight-through: z_q_out == z_q in value)
        float errsum = 0.f;
        const float* er = emb + (size_t)idx * DIM;
        float* zq = out + OFF_ZQ + (size_t)b * BHW + hw0 + tid;
        #pragma unroll
        for (int c = 0; c < DIM; ++c) {
            float e  = __ldg(er + c);
            float zv = zs[c][tid];
            float df = e - zv;
            errsum   = fmaf(df, df, errsum);
            zq[(size_t)c * HW] = e;
        }
        #pragma unroll
        for (int o = 16; o > 0; o >>= 1)
            errsum += __shfl_down_sync(0xFFFFFFFFu, errsum, o);
        if ((tid & 31) == 0) atomicAdd(&d_loss, errsum);
    }

    // ---------------- last-block finalize (perplexity + loss scalars) ----------------
    __threadfence();
    __syncthreads();
    if (tid == 0) last_s = (atomicAdd(&d_done, 1u) == NBLK - 1) ? 1 : 0;
    __syncthreads();
    if (last_s) {
        float part = 0.f;
        #pragma unroll
        for (int i = 0; i < 8; ++i) {
            int c = tid + i * 128;
            unsigned cnt = d_count[c];
            d_count[c] = 0u;                       // reset for graph replay
            float em = (float)cnt * (1.0f / 32768.0f);
            part += em * logf(em + 1e-10f);
        }
        #pragma unroll
        for (int o = 16; o > 0; o >>= 1)
            part += __shfl_down_sync(0xFFFFFFFFu, part, o);
        if ((tid & 31) == 0) warp_s[tid >> 5] = part;
        __syncthreads();
        if (tid == 0) {
            float w = warp_s[0] + warp_s[1] + warp_s[2] + warp_s[3];
            out[OFF_PERP] = expf(-w);
            out[OFF_LOSS] = 1.25f * d_loss * (1.0f / 2097152.0f);
            d_loss = 0.f;                          // reset for graph replay
            d_done = 0u;
        }
    }
}

// ---------------------------------------------------------------- launch
extern "C" void kernel_launch(void* const* d_in, const int* in_sizes, int n_in,
                              void* d_out, int out_size) {
    const float* z   = (const float*)d_in[0];
    const float* emb = (const float*)d_in[1];
    float*       out = (float*)d_out;

    prep_kernel<<<16, 128>>>(emb);
    vq_main_kernel<<<NBLK, 128>>>(z, emb, out);
}

// round 12
// speedup vs baseline: 1.0886x; 1.0886x over previous
#include <cuda_runtime.h>
#include <cstdint>

// Problem constants
#define NPTS   32768            // 32 * 32 * 32 points
#define DIM    64               // embedding dim
#define NE     1024             // codebook size
#define HW     1024             // 32*32 spatial
#define BHW    65536            // 64 channels * 1024 hw (per-batch stride in z)
#define PTSB   64               // points per block
#define HCH    64               // codes per half-chunk
#define NH     16               // number of half-chunks

// Output layout (flat concat of reference return tuple, float32):
// loss[1], z_q[2097152], perplexity[1], min_encodings[33554432], indices[32768]
#define OFF_LOSS 0ULL
#define OFF_ZQ   1ULL
#define OFF_PERP 2097153ULL
#define OFF_ENC  2097154ULL
#define OFF_IDX  35651586ULL

__device__ float        d_esq[NE];
__device__ float        d_est[DIM * NE];   // transposed codebook [k][c]
__device__ unsigned int d_count[NE];
__device__ float        d_loss;

// ---------------------------------------------------------------- helpers
struct __align__(16) ull2 { unsigned long long a, b; };

static __device__ __forceinline__ unsigned long long pk2(float v) {
    unsigned long long r;
    asm("mov.b64 %0, {%1,%2};" : "=l"(r) : "f"(v), "f"(v));
    return r;
}
static __device__ __forceinline__ void ffma2(unsigned long long& d,
                                             unsigned long long a,
                                             unsigned long long b) {
    asm("fma.rn.f32x2 %0, %1, %2, %0;" : "+l"(d) : "l"(a), "l"(b));
}
static __device__ __forceinline__ float2 upk(unsigned long long v) {
    float2 f;
    asm("mov.b64 {%0,%1}, %2;" : "=f"(f.x), "=f"(f.y) : "l"(v));
    return f;
}
static __device__ __forceinline__ unsigned int ordf(float x) {
    unsigned int b = __float_as_uint(x);
    return b ^ (unsigned int)(((int)b >> 31) | 0x80000000);
}
static __device__ __forceinline__ void cpasync16(unsigned int dst_smem,
                                                 const void* src) {
    asm volatile("cp.async.ca.shared.global [%0], [%1], 16;"
                 :: "r"(dst_smem), "l"(src));
}
#define CP_COMMIT() asm volatile("cp.async.commit_group;" ::: "memory")
#define CP_WAIT0()  asm volatile("cp.async.wait_group 0;" ::: "memory")

// ---------------------------------------------------------------- prep
// 16 blocks x 128 threads; block handles 64 codes. Verified ~5.3us.
__global__ void prep_kernel(const float* __restrict__ emb) {
    __shared__ float sb[64][DIM + 1];
    const int tid = threadIdx.x;
    const int c0  = blockIdx.x * 64;

    const float4* src = (const float4*)(emb + (size_t)c0 * DIM);
    #pragma unroll
    for (int i = 0; i < 8; ++i) {
        int f  = i * 128 + tid;
        int c  = f >> 4;
        int k4 = f & 15;
        float4 v = src[f];
        sb[c][k4 * 4 + 0] = v.x;
        sb[c][k4 * 4 + 1] = v.y;
        sb[c][k4 * 4 + 2] = v.z;
        sb[c][k4 * 4 + 3] = v.w;
    }
    __syncthreads();

    if (tid < 64) {
        const int c = c0 + tid;
        float s = 0.f;
        #pragma unroll
        for (int k = 0; k < DIM; ++k) {
            float v = sb[tid][k];
            s = __fadd_rn(s, __fmul_rn(v, v));
            d_est[k * NE + c] = v;
        }
        d_esq[c]   = s;
        d_count[c] = 0u;
        if (c == 0) d_loss = 0.f;
    }
}

// ---------------------------------------------------------------- main fused kernel
// Exact R7 shell (measured 127.07us total) + software-pipelined inner loop:
// preload k+1's z/es into registers before k's 16 FFMA2 -> LDS latency hidden.
// block: 128 threads = 16 pt-groups (pt_t, 4 pts) x 8 code-groups (cg, 8 codes)
// block tile: 64 points x 64 codes per half-chunk (16 half-chunks -> 1024 codes)
// thread tile: 4 points x 8 codes (4 f32x2 code-pairs)  -> acc[4][4] u64 = 64 regs
__global__ void __launch_bounds__(128, 4)
vq_main_kernel(const float* __restrict__ z, const float* __restrict__ emb,
               float* __restrict__ out)
{
    __shared__ __align__(16) float zs[DIM][PTSB];      // natural [k][pt], 16 KB
    __shared__ __align__(16) float es[2][DIM][HCH];    // double buf, 2x16 KB
    __shared__ float zsq_s[PTSB];
    __shared__ unsigned long long red[8][PTSB];        // 4 KB

    const int tid  = threadIdx.x;
    const int pt_t = tid & 15;    // 0..15 point group (4 pts each)
    const int cg   = tid >> 4;    // 0..7  code group  (8 codes each)
    const int pt0  = blockIdx.x * PTSB;
    const int b    = pt0 >> 10;
    const int hw0  = pt0 & 1023;
    const float* zb = z + (size_t)b * BHW + hw0;

    // issue es half-chunk 0 fetch immediately (overlaps zs load)
    {
        unsigned int dst0 = (unsigned int)__cvta_generic_to_shared(&es[0][0][0]);
        #pragma unroll
        for (int i = 0; i < 8; ++i) {
            int f = i * 128 + tid;
            int k = f >> 4, c16 = f & 15;
            cpasync16(dst0 + (unsigned)(k * HCH + c16 * 4) * 4u,
                      &d_est[(size_t)k * NE + 0 * HCH + c16 * 4]);
        }
        CP_COMMIT();
    }

    // load z tile (coalesced), natural layout
    #pragma unroll
    for (int i = 0; i < 32; ++i) {
        int f = i * 128 + tid;
        int k = f >> 6, p = f & 63;
        zs[k][p] = zb[(size_t)k * HW + p];
    }

    // one-hot region head/tail scalars (base%4==2); float4 body interleaved below
    float* encb = out + OFF_ENC + (size_t)pt0 * NE;    // 65536 floats
    float4* e4  = (float4*)(encb + 2);                 // 16383 float4s
    if (tid == 0) {
        encb[0] = 0.f; encb[1] = 0.f;
        encb[65534] = 0.f; encb[65535] = 0.f;
    }
    __syncthreads();

    // per-point ||z||^2, sequential fp32 rn (matches reference rounding)
    if (tid < PTSB) {
        float s = 0.f;
        #pragma unroll
        for (int k = 0; k < DIM; ++k) {
            float v = zs[k][tid];
            s = __fadd_rn(s, __fmul_rn(v, v));
        }
        zsq_s[tid] = s;
    }

    unsigned long long best[4];
    #pragma unroll
    for (int p = 0; p < 4; ++p) best[p] = 0xFFFFFFFFFFFFFFFFULL;

    for (int h = 0; h < NH; ++h) {
        const int buf = h & 1;
        CP_WAIT0();            // this thread's half-chunk h slice landed
        __syncthreads();       // all slices visible; all done computing h-1

        // prefetch half-chunk h+1 into the other buffer (overlaps compute)
        if (h + 1 < NH) {
            unsigned int dstn = (unsigned int)__cvta_generic_to_shared(
                &es[buf ^ 1][0][0]);
            #pragma unroll
            for (int i = 0; i < 8; ++i) {
                int f = i * 128 + tid;
                int k = f >> 4, c16 = f & 15;
                cpasync16(dstn + (unsigned)(k * HCH + c16 * 4) * 4u,
                          &d_est[(size_t)k * NE + (h + 1) * HCH + c16 * 4]);
            }
        }
        CP_COMMIT();           // commit (possibly empty) group each iter

        // interleaved one-hot zero-fill slice (drains on HBM under the FMAs)
        #pragma unroll
        for (int i = 0; i < 8; ++i) {
            int j = h * 1024 + i * 128 + tid;
            if (j < 16383) e4[j] = make_float4(0.f, 0.f, 0.f, 0.f);
        }

        unsigned long long acc[4][4];      // [point][code-pair]
        #pragma unroll
        for (int p = 0; p < 4; ++p)
            #pragma unroll
            for (int j = 0; j < 4; ++j) acc[p][j] = 0ULL;

        // ---- software-pipelined dot loop: loads for k+1 issued before k's FMAs
        float4 zc  = *(const float4*)&zs[0][pt_t * 4];
        ull2   eAc = *(const ull2*)&es[buf][0][cg * 8];
        ull2   eBc = *(const ull2*)&es[buf][0][cg * 8 + 4];

        #pragma unroll 8
        for (int k = 0; k < DIM; ++k) {
            const int kn = (k + 1 < DIM) ? (k + 1) : (DIM - 1);
            float4 zn  = *(const float4*)&zs[kn][pt_t * 4];
            ull2   eAn = *(const ull2*)&es[buf][kn][cg * 8];
            ull2   eBn = *(const ull2*)&es[buf][kn][cg * 8 + 4];

            unsigned long long z0 = pk2(zc.x), z1 = pk2(zc.y);
            unsigned long long z2 = pk2(zc.z), z3 = pk2(zc.w);
            ffma2(acc[0][0], z0, eAc.a); ffma2(acc[0][1], z0, eAc.b);
            ffma2(acc[0][2], z0, eBc.a); ffma2(acc[0][3], z0, eBc.b);
            ffma2(acc[1][0], z1, eAc.a); ffma2(acc[1][1], z1, eAc.b);
            ffma2(acc[1][2], z1, eBc.a); ffma2(acc[1][3], z1, eBc.b);
            ffma2(acc[2][0], z2, eAc.a); ffma2(acc[2][1], z2, eAc.b);
            ffma2(acc[2][2], z2, eBc.a); ffma2(acc[2][3], z2, eBc.b);
            ffma2(acc[3][0], z3, eAc.a); ffma2(acc[3][1], z3, eAc.b);
            ffma2(acc[3][2], z3, eBc.a); ffma2(acc[3][3], z3, eBc.b);

            zc = zn; eAc = eAn; eBc = eBn;
        }

        // distances + running argmin (u64 key -> first-index tie-break)
        const int cbase = h * HCH + cg * 8;
        #pragma unroll
        for (int j = 0; j < 4; ++j) {
            float esq0 = __ldg(&d_esq[cbase + 2 * j]);
            float esq1 = __ldg(&d_esq[cbase + 2 * j + 1]);
            #pragma unroll
            for (int p = 0; p < 4; ++p) {
                float zq2 = zsq_s[pt_t * 4 + p];
                float2 dot = upk(acc[p][j]);
                {
                    float d = __fadd_rn(__fadd_rn(zq2, esq0), -2.0f * dot.x);
                    unsigned long long k64 =
                        ((unsigned long long)ordf(d) << 32) | (unsigned)(cbase + 2 * j);
                    if (k64 < best[p]) best[p] = k64;
                }
                {
                    float d = __fadd_rn(__fadd_rn(zq2, esq1), -2.0f * dot.y);
                    unsigned long long k64 =
                        ((unsigned long long)ordf(d) << 32) | (unsigned)(cbase + 2 * j + 1);
                    if (k64 < best[p]) best[p] = k64;
                }
            }
        }
    }

    // cross-thread argmin reduction per point (8 code-groups per point)
    __syncthreads();
    #pragma unroll
    for (int p = 0; p < 4; ++p) red[cg][pt_t * 4 + p] = best[p];
    __syncthreads();

    if (tid < PTSB) {
        unsigned long long bk = red[0][tid];
        #pragma unroll
        for (int t = 1; t < 8; ++t) {
            unsigned long long v = red[t][tid];
            if (v < bk) bk = v;
        }
        int idx = (int)(unsigned int)bk;
        int n   = pt0 + tid;

        out[OFF_IDX + n] = (float)idx;
        atomicAdd(&d_count[idx], 1u);
        out[OFF_ENC + (unsigned long long)n * NE + (unsigned)idx] = 1.0f;

        // z_q gather + loss partial (straight-through: z_q_out == z_q in value)
        float errsum = 0.f;
        const float* er = emb + (size_t)idx * DIM;
        float* zq = out + OFF_ZQ + (size_t)b * BHW + hw0 + tid;
        #pragma unroll
        for (int c = 0; c < DIM; ++c) {
            float e  = __ldg(er + c);
            float zv = zs[c][tid];
            float df = e - zv;
            errsum   = fmaf(df, df, errsum);
            zq[(size_t)c * HW] = e;
        }
        #pragma unroll
        for (int o = 16; o > 0; o >>= 1)
            errsum += __shfl_down_sync(0xFFFFFFFFu, errsum, o);
        if ((tid & 31) == 0) atomicAdd(&d_loss, errsum);
    }
}

// ---------------------------------------------------------------- finalize scalars
__global__ void finalize_kernel(float* __restrict__ out) {
    __shared__ float warp_s[32];
    int t = threadIdx.x;  // 1024 threads
    float em = (float)d_count[t] * (1.0f / 32768.0f);
    float v  = em * logf(em + 1e-10f);
    #pragma unroll
    for (int o = 16; o > 0; o >>= 1) v += __shfl_down_sync(0xFFFFFFFFu, v, o);
    if ((t & 31) == 0) warp_s[t >> 5] = v;
    __syncthreads();
    if (t < 32) {
        float w = warp_s[t];
        #pragma unroll
        for (int o = 16; o > 0; o >>= 1) w += __shfl_down_sync(0xFFFFFFFFu, w, o);
        if (t == 0) {
            out[OFF_PERP] = expf(-w);
            out[OFF_LOSS] = 1.25f * d_loss * (1.0f / 2097152.0f);
        }
    }
}

// ---------------------------------------------------------------- launch
extern "C" void kernel_launch(void* const* d_in, const int* in_sizes, int n_in,
                              void* d_out, int out_size) {
    const float* z   = (const float*)d_in[0];
    const float* emb = (const float*)d_in[1];
    float*       out = (float*)d_out;

    prep_kernel<<<16, 128>>>(emb);
    vq_main_kernel<<<NPTS / PTSB, 128>>>(z, emb, out);
    finalize_kernel<<<1, 1024>>>(out);
}

// round 13
// speedup vs baseline: 1.1376x; 1.0450x over previous
#include <cuda_runtime.h>
#include <cstdint>

// Problem constants
#define NPTS   32768            // 32 * 32 * 32 points
#define DIM    64               // embedding dim
#define NE     1024             // codebook size
#define HW     1024             // 32*32 spatial
#define BHW    65536            // 64 channels * 1024 hw (per-batch stride in z)
#define PTSB   64               // points per tile
#define HCH    64               // codes per half-chunk
#define NH     8                // half-chunks per CTA (512 codes)
#define NTILE  (NPTS / PTSB)    // 512 point tiles
#define NBLK   (NTILE * 2)      // 1024 CTAs (2 code-halves per tile)

// Output layout (flat concat of reference return tuple, float32):
// loss[1], z_q[2097152], perplexity[1], min_encodings[33554432], indices[32768]
#define OFF_LOSS 0ULL
#define OFF_ZQ   1ULL
#define OFF_PERP 2097153ULL
#define OFF_ENC  2097154ULL
#define OFF_IDX  35651586ULL

__device__ float              d_esq[NE];
__device__ float              d_est[DIM * NE];   // transposed codebook [k][c]
__device__ unsigned int       d_count[NE];
__device__ unsigned long long d_best[NPTS];      // argmin keys (atomicMin merge)
__device__ unsigned int       d_tile[NTILE];     // per-tile arrival tickets
__device__ float              d_loss;
__device__ unsigned int       d_done;

// ---------------------------------------------------------------- helpers
struct __align__(16) ull2 { unsigned long long a, b; };

static __device__ __forceinline__ unsigned long long pk2(float v) {
    unsigned long long r;
    asm("mov.b64 %0, {%1,%2};" : "=l"(r) : "f"(v), "f"(v));
    return r;
}
static __device__ __forceinline__ void ffma2(unsigned long long& d,
                                             unsigned long long a,
                                             unsigned long long b) {
    asm("fma.rn.f32x2 %0, %1, %2, %0;" : "+l"(d) : "l"(a), "l"(b));
}
static __device__ __forceinline__ float2 upk(unsigned long long v) {
    float2 f;
    asm("mov.b64 {%0,%1}, %2;" : "=f"(f.x), "=f"(f.y) : "l"(v));
    return f;
}
static __device__ __forceinline__ unsigned int ordf(float x) {
    unsigned int b = __float_as_uint(x);
    return b ^ (unsigned int)(((int)b >> 31) | 0x80000000);
}
static __device__ __forceinline__ void cpasync16(unsigned int dst_smem,
                                                 const void* src) {
    asm volatile("cp.async.ca.shared.global [%0], [%1], 16;"
                 :: "r"(dst_smem), "l"(src));
}
#define CP_COMMIT() asm volatile("cp.async.commit_group;" ::: "memory")
#define CP_WAIT0()  asm volatile("cp.async.wait_group 0;" ::: "memory")

// ---------------------------------------------------------------- prep
// 32 blocks x 128 threads. Blocks 0-15: codebook transpose + ||e||^2 + counters.
// All blocks: re-init d_best / d_tile (graph-replay safe).
__global__ void prep_kernel(const float* __restrict__ emb) {
    __shared__ float sb[64][DIM + 1];
    const int tid = threadIdx.x;
    const int bid = blockIdx.x;
    const int g   = bid * 128 + tid;

    // reset merge state every launch
    #pragma unroll
    for (int i = 0; i < 8; ++i) d_best[g + i * 4096] = 0xFFFFFFFFFFFFFFFFULL;
    if (g < NTILE) d_tile[g] = 0u;
    if (g == 0) { d_loss = 0.f; d_done = 0u; }

    if (bid < 16) {
        const int c0 = bid * 64;
        const float4* src = (const float4*)(emb + (size_t)c0 * DIM);
        #pragma unroll
        for (int i = 0; i < 8; ++i) {
            int f  = i * 128 + tid;
            int c  = f >> 4;
            int k4 = f & 15;
            float4 v = src[f];
            sb[c][k4 * 4 + 0] = v.x;
            sb[c][k4 * 4 + 1] = v.y;
            sb[c][k4 * 4 + 2] = v.z;
            sb[c][k4 * 4 + 3] = v.w;
        }
        __syncthreads();

        if (tid < 64) {
            const int c = c0 + tid;
            float s = 0.f;
            #pragma unroll
            for (int k = 0; k < DIM; ++k) {
                float v = sb[tid][k];
                s = __fadd_rn(s, __fmul_rn(v, v));
                d_est[k * NE + c] = v;
            }
            d_esq[c]   = s;
            d_count[c] = 0u;
        }
    }
}

// ---------------------------------------------------------------- main fused kernel
// CTA = (tile, codeHalf): 64 points x 512 codes, R12's proven pipelined loop.
// 128 threads = 16 pt-groups (pt_t, 4 pts) x 8 code-groups (cg, 8 codes).
__global__ void __launch_bounds__(128, 4)
vq_main_kernel(const float* __restrict__ z, const float* __restrict__ emb,
               float* __restrict__ out)
{
    __shared__ __align__(16) float zs[DIM][PTSB];      // [k][pt] 16 KB
    __shared__ __align__(16) float es[2][DIM][HCH];    // double buf, 2x16 KB
    __shared__ float zsq_s[PTSB];
    __shared__ unsigned long long red[8][PTSB];        // 4 KB
    __shared__ float warp_s[4];
    __shared__ int   flag_s;

    const int tid  = threadIdx.x;
    const int pt_t = tid & 15;    // 0..15 point group (4 pts)
    const int cg   = tid >> 4;    // 0..7  code group (8 codes)
    const int tile = blockIdx.x >> 1;
    const int chal = blockIdx.x & 1;          // code half
    const int c0   = chal * 512;
    const int pt0  = tile * PTSB;
    const int b    = pt0 >> 10;
    const int hw0  = pt0 & 1023;
    const float* zb = z + (size_t)b * BHW + hw0;

    // issue es half-chunk 0 fetch immediately
    {
        unsigned int dst0 = (unsigned int)__cvta_generic_to_shared(&es[0][0][0]);
        #pragma unroll
        for (int i = 0; i < 8; ++i) {
            int f = i * 128 + tid;
            int k = f >> 4, c16 = f & 15;
            cpasync16(dst0 + (unsigned)(k * HCH + c16 * 4) * 4u,
                      &d_est[(size_t)k * NE + c0 + c16 * 4]);
        }
        CP_COMMIT();
    }

    // load z tile (coalesced), natural layout
    #pragma unroll
    for (int i = 0; i < 32; ++i) {
        int f = i * 128 + tid;
        int k = f >> 6, p = f & 63;
        zs[k][p] = zb[(size_t)k * HW + p];
    }

    // one-hot region: this CTA zero-fills its code-half of the tile's rows
    float* encb = out + OFF_ENC + (size_t)pt0 * NE;    // 65536 floats
    float4* e4  = (float4*)(encb + 2);                 // 16383 float4s
    if (tid == 0) {
        if (chal == 0) { encb[0] = 0.f; encb[1] = 0.f; }
        else           { encb[65534] = 0.f; encb[65535] = 0.f; }
    }
    __syncthreads();

    // per-point ||z||^2, sequential fp32 rn (matches reference rounding)
    if (tid < PTSB) {
        float s = 0.f;
        #pragma unroll
        for (int k = 0; k < DIM; ++k) {
            float v = zs[k][tid];
            s = __fadd_rn(s, __fmul_rn(v, v));
        }
        zsq_s[tid] = s;
    }

    unsigned long long best[4];
    #pragma unroll
    for (int p = 0; p < 4; ++p) best[p] = 0xFFFFFFFFFFFFFFFFULL;

    for (int h = 0; h < NH; ++h) {
        const int buf = h & 1;
        CP_WAIT0();
        __syncthreads();

        if (h + 1 < NH) {
            unsigned int dstn = (unsigned int)__cvta_generic_to_shared(
                &es[buf ^ 1][0][0]);
            #pragma unroll
            for (int i = 0; i < 8; ++i) {
                int f = i * 128 + tid;
                int k = f >> 4, c16 = f & 15;
                cpasync16(dstn + (unsigned)(k * HCH + c16 * 4) * 4u,
                          &d_est[(size_t)k * NE + c0 + (h + 1) * HCH + c16 * 4]);
            }
        }
        CP_COMMIT();

        // interleaved zero-fill slice of this CTA's half (8191/8192 float4s)
        #pragma unroll
        for (int i = 0; i < 8; ++i) {
            int j = chal * 8192 + h * 1024 + i * 128 + tid;
            if (j < 16383) e4[j] = make_float4(0.f, 0.f, 0.f, 0.f);
        }

        unsigned long long acc[4][4];      // [point][code-pair]
        #pragma unroll
        for (int p = 0; p < 4; ++p)
            #pragma unroll
            for (int j = 0; j < 4; ++j) acc[p][j] = 0ULL;

        // software-pipelined dot loop (k+1 loads before k's FMAs)
        float4 zc  = *(const float4*)&zs[0][pt_t * 4];
        ull2   eAc = *(const ull2*)&es[buf][0][cg * 8];
        ull2   eBc = *(const ull2*)&es[buf][0][cg * 8 + 4];

        #pragma unroll 8
        for (int k = 0; k < DIM; ++k) {
            const int kn = (k + 1 < DIM) ? (k + 1) : (DIM - 1);
            float4 zn  = *(const float4*)&zs[kn][pt_t * 4];
            ull2   eAn = *(const ull2*)&es[buf][kn][cg * 8];
            ull2   eBn = *(const ull2*)&es[buf][kn][cg * 8 + 4];

            unsigned long long z0 = pk2(zc.x), z1 = pk2(zc.y);
            unsigned long long z2 = pk2(zc.z), z3 = pk2(zc.w);
            ffma2(acc[0][0], z0, eAc.a); ffma2(acc[0][1], z0, eAc.b);
            ffma2(acc[0][2], z0, eBc.a); ffma2(acc[0][3], z0, eBc.b);
            ffma2(acc[1][0], z1, eAc.a); ffma2(acc[1][1], z1, eAc.b);
            ffma2(acc[1][2], z1, eBc.a); ffma2(acc[1][3], z1, eBc.b);
            ffma2(acc[2][0], z2, eAc.a); ffma2(acc[2][1], z2, eAc.b);
            ffma2(acc[2][2], z2, eBc.a); ffma2(acc[2][3], z2, eBc.b);
            ffma2(acc[3][0], z3, eAc.a); ffma2(acc[3][1], z3, eAc.b);
            ffma2(acc[3][2], z3, eBc.a); ffma2(acc[3][3], z3, eBc.b);

            zc = zn; eAc = eAn; eBc = eBn;
        }

        // distances + running argmin
        const int cbase = c0 + h * HCH + cg * 8;
        #pragma unroll
        for (int j = 0; j < 4; ++j) {
            float esq0 = __ldg(&d_esq[cbase + 2 * j]);
            float esq1 = __ldg(&d_esq[cbase + 2 * j + 1]);
            #pragma unroll
            for (int p = 0; p < 4; ++p) {
                float zq2 = zsq_s[pt_t * 4 + p];
                float2 dot = upk(acc[p][j]);
                {
                    float d = __fadd_rn(__fadd_rn(zq2, esq0), -2.0f * dot.x);
                    unsigned long long k64 =
                        ((unsigned long long)ordf(d) << 32) | (unsigned)(cbase + 2 * j);
                    if (k64 < best[p]) best[p] = k64;
                }
                {
                    float d = __fadd_rn(__fadd_rn(zq2, esq1), -2.0f * dot.y);
                    unsigned long long k64 =
                        ((unsigned long long)ordf(d) << 32) | (unsigned)(cbase + 2 * j + 1);
                    if (k64 < best[p]) best[p] = k64;
                }
            }
        }
    }

    // cross-thread argmin reduction within CTA, then merge across the 2 CTAs
    __syncthreads();
    #pragma unroll
    for (int p = 0; p < 4; ++p) red[cg][pt_t * 4 + p] = best[p];
    __syncthreads();

    if (tid < PTSB) {
        unsigned long long bk = red[0][tid];
        #pragma unroll
        for (int t = 1; t < 8; ++t) {
            unsigned long long v = red[t][tid];
            if (v < bk) bk = v;
        }
        atomicMin(&d_best[pt0 + tid], bk);
    }

    // tile ticket: second arriving CTA runs the epilogue
    __threadfence();
    __syncthreads();
    if (tid == 0) flag_s = (atomicAdd(&d_tile[tile], 1u) == 1) ? 1 : 0;
    __syncthreads();
    if (!flag_s) return;

    if (tid < PTSB) {
        int n   = pt0 + tid;
        unsigned long long bk =
            *((volatile unsigned long long*)&d_best[n]);   // final (both fenced)
        int idx = (int)(unsigned int)bk;

        out[OFF_IDX + n] = (float)idx;
        atomicAdd(&d_count[idx], 1u);
        out[OFF_ENC + (unsigned long long)n * NE + (unsigned)idx] = 1.0f;

        // z_q gather + loss partial
        float errsum = 0.f;
        const float* er = emb + (size_t)idx * DIM;
        float* zq = out + OFF_ZQ + (size_t)b * BHW + hw0 + tid;
        #pragma unroll
        for (int c = 0; c < DIM; ++c) {
            float e  = __ldg(er + c);
            float zv = zs[c][tid];
            float df = e - zv;
            errsum   = fmaf(df, df, errsum);
            zq[(size_t)c * HW] = e;
        }
        #pragma unroll
        for (int o = 16; o > 0; o >>= 1)
            errsum += __shfl_down_sync(0xFFFFFFFFu, errsum, o);
        if ((tid & 31) == 0) atomicAdd(&d_loss, errsum);
    }

    // global ticket: last epilogue CTA computes perplexity + loss scalars
    __threadfence();
    __syncthreads();
    if (tid == 0) flag_s = (atomicAdd(&d_done, 1u) == NTILE - 1) ? 1 : 0;
    __syncthreads();
    if (flag_s) {
        float part = 0.f;
        #pragma unroll
        for (int i = 0; i < 8; ++i) {
            int c = tid + i * 128;
            float em = (float)*((volatile unsigned int*)&d_count[c])
                       * (1.0f / 32768.0f);
            part += em * logf(em + 1e-10f);
        }
        #pragma unroll
        for (int o = 16; o > 0; o >>= 1)
            part += __shfl_down_sync(0xFFFFFFFFu, part, o);
        if ((tid & 31) == 0) warp_s[tid >> 5] = part;
        __syncthreads();
        if (tid == 0) {
            float w = warp_s[0] + warp_s[1] + warp_s[2] + warp_s[3];
            out[OFF_PERP] = expf(-w);
            out[OFF_LOSS] = 1.25f * (*((volatile float*)&d_loss))
                            * (1.0f / 2097152.0f);
        }
    }
}

// ---------------------------------------------------------------- launch
extern "C" void kernel_launch(void* const* d_in, const int* in_sizes, int n_in,
                              void* d_out, int out_size) {
    const float* z   = (const float*)d_in[0];
    const float* emb = (const float*)d_in[1];
    float*       out = (float*)d_out;

    prep_kernel<<<32, 128>>>(emb);
    vq_main_kernel<<<NBLK, 128>>>(z, emb, out);
}

// round 14
// speedup vs baseline: 1.1474x; 1.0086x over previous
#include <cuda_runtime.h>
#include <cstdint>

// Problem constants
#define NPTS   32768            // 32 * 32 * 32 points
#define DIM    64               // embedding dim
#define NE     1024             // codebook size
#define HW     1024             // 32*32 spatial
#define BHW    65536            // 64 channels * 1024 hw (per-batch stride in z)
#define PTSB   64               // points per tile
#define HCH    64               // codes per chunk
#define NH     4                // chunks per CTA (256 codes)
#define NTILE  (NPTS / PTSB)    // 512 point tiles
#define NSPLIT 4                // code-split CTAs per tile
#define NBLK   (NTILE * NSPLIT) // 2048 CTAs

// Output layout (flat concat of reference return tuple, float32):
// loss[1], z_q[2097152], perplexity[1], min_encodings[33554432], indices[32768]
#define OFF_LOSS 0ULL
#define OFF_ZQ   1ULL
#define OFF_PERP 2097153ULL
#define OFF_ENC  2097154ULL
#define OFF_IDX  35651586ULL

__device__ float              d_esq[NE];
__device__ float              d_est[DIM * NE];   // transposed codebook [k][c]
__device__ unsigned int       d_count[NE];
__device__ unsigned long long d_best[NPTS];      // argmin keys (atomicMin merge)
__device__ unsigned int       d_tile[NTILE];     // per-tile arrival tickets
__device__ float              d_loss;
__device__ unsigned int       d_done;

// ---------------------------------------------------------------- helpers
struct __align__(16) ull2 { unsigned long long a, b; };

static __device__ __forceinline__ unsigned long long pk2(float v) {
    unsigned long long r;
    asm("mov.b64 %0, {%1,%2};" : "=l"(r) : "f"(v), "f"(v));
    return r;
}
static __device__ __forceinline__ void ffma2(unsigned long long& d,
                                             unsigned long long a,
                                             unsigned long long b) {
    asm("fma.rn.f32x2 %0, %1, %2, %0;" : "+l"(d) : "l"(a), "l"(b));
}
static __device__ __forceinline__ float2 upk(unsigned long long v) {
    float2 f;
    asm("mov.b64 {%0,%1}, %2;" : "=f"(f.x), "=f"(f.y) : "l"(v));
    return f;
}
static __device__ __forceinline__ unsigned int ordf(float x) {
    unsigned int b = __float_as_uint(x);
    return b ^ (unsigned int)(((int)b >> 31) | 0x80000000);
}
static __device__ __forceinline__ void cpasync16(unsigned int dst_smem,
                                                 const void* src) {
    asm volatile("cp.async.ca.shared.global [%0], [%1], 16;"
                 :: "r"(dst_smem), "l"(src));
}
#define CP_COMMIT() asm volatile("cp.async.commit_group;" ::: "memory")
#define CP_WAIT0()  asm volatile("cp.async.wait_group 0;" ::: "memory")

// ---------------------------------------------------------------- prep
// 32 blocks x 128 threads. Blocks 0-15: codebook transpose + ||e||^2 + counters.
// All blocks: re-init d_best / d_tile (graph-replay safe).
__global__ void prep_kernel(const float* __restrict__ emb) {
    __shared__ float sb[64][DIM + 1];
    const int tid = threadIdx.x;
    const int bid = blockIdx.x;
    const int g   = bid * 128 + tid;

    // reset merge state every launch
    #pragma unroll
    for (int i = 0; i < 8; ++i) d_best[g + i * 4096] = 0xFFFFFFFFFFFFFFFFULL;
    if (g < NTILE) d_tile[g] = 0u;
    if (g == 0) { d_loss = 0.f; d_done = 0u; }

    if (bid < 16) {
        const int c0 = bid * 64;
        const float4* src = (const float4*)(emb + (size_t)c0 * DIM);
        #pragma unroll
        for (int i = 0; i < 8; ++i) {
            int f  = i * 128 + tid;
            int c  = f >> 4;
            int k4 = f & 15;
            float4 v = src[f];
            sb[c][k4 * 4 + 0] = v.x;
            sb[c][k4 * 4 + 1] = v.y;
            sb[c][k4 * 4 + 2] = v.z;
            sb[c][k4 * 4 + 3] = v.w;
        }
        __syncthreads();

        if (tid < 64) {
            const int c = c0 + tid;
            float s = 0.f;
            #pragma unroll
            for (int k = 0; k < DIM; ++k) {
                float v = sb[tid][k];
                s = __fadd_rn(s, __fmul_rn(v, v));
                d_est[k * NE + c] = v;
            }
            d_esq[c]   = s;
            d_count[c] = 0u;
        }
    }
}

// ---------------------------------------------------------------- main fused kernel
// CTA = (tile, codeQuarter): 64 points x 256 codes, R13's inner loop, occ 5.
// 128 threads = 16 pt-groups (pt_t, 4 pts) x 8 code-groups (cg, 8 codes).
__global__ void __launch_bounds__(128, 5)
vq_main_kernel(const float* __restrict__ z, const float* __restrict__ emb,
               float* __restrict__ out)
{
    __shared__ __align__(16) float zs[DIM][PTSB];      // [k][pt] 16 KB
    __shared__ __align__(16) float es[DIM][HCH];       // single buf, 16 KB
    __shared__ float zsq_s[PTSB];
    __shared__ unsigned long long red[8][PTSB];        // 4 KB
    __shared__ float warp_s[4];
    __shared__ int   flag_s;

    const int tid  = threadIdx.x;
    const int pt_t = tid & 15;    // 0..15 point group (4 pts)
    const int cg   = tid >> 4;    // 0..7  code group (8 codes)
    const int tile = blockIdx.x >> 2;
    const int chal = blockIdx.x & 3;          // code quarter
    const int c0   = chal * 256;
    const int pt0  = tile * PTSB;
    const int b    = pt0 >> 10;
    const int hw0  = pt0 & 1023;
    const float* zb = z + (size_t)b * BHW + hw0;

    // issue es chunk 0 fetch immediately (overlaps zs load)
    {
        unsigned int dst0 = (unsigned int)__cvta_generic_to_shared(&es[0][0]);
        #pragma unroll
        for (int i = 0; i < 8; ++i) {
            int f = i * 128 + tid;
            int k = f >> 4, c16 = f & 15;
            cpasync16(dst0 + (unsigned)(k * HCH + c16 * 4) * 4u,
                      &d_est[(size_t)k * NE + c0 + c16 * 4]);
        }
        CP_COMMIT();
    }

    // load z tile (coalesced), natural layout
    #pragma unroll
    for (int i = 0; i < 32; ++i) {
        int f = i * 128 + tid;
        int k = f >> 6, p = f & 63;
        zs[k][p] = zb[(size_t)k * HW + p];
    }

    // one-hot region: this CTA zero-fills its quarter of the tile's rows
    float* encb = out + OFF_ENC + (size_t)pt0 * NE;    // 65536 floats
    float4* e4  = (float4*)(encb + 2);                 // 16383 float4s
    if (tid == 0) {
        if (chal == 0) { encb[0] = 0.f; encb[1] = 0.f; }
        if (chal == 3) { encb[65534] = 0.f; encb[65535] = 0.f; }
    }
    __syncthreads();

    // per-point ||z||^2, sequential fp32 rn (matches reference rounding)
    if (tid < PTSB) {
        float s = 0.f;
        #pragma unroll
        for (int k = 0; k < DIM; ++k) {
            float v = zs[k][tid];
            s = __fadd_rn(s, __fmul_rn(v, v));
        }
        zsq_s[tid] = s;
    }

    unsigned long long best[4];
    #pragma unroll
    for (int p = 0; p < 4; ++p) best[p] = 0xFFFFFFFFFFFFFFFFULL;

    for (int h = 0; h < NH; ++h) {
        CP_WAIT0();            // chunk h landed
        __syncthreads();       // visible to all (also covers zsq_s on h=0)

        // interleaved zero-fill slice of this CTA's quarter
        #pragma unroll
        for (int i = 0; i < 8; ++i) {
            int j = chal * 4096 + h * 1024 + i * 128 + tid;
            if (j < 16383) e4[j] = make_float4(0.f, 0.f, 0.f, 0.f);
        }

        unsigned long long acc[4][4];      // [point][code-pair]
        #pragma unroll
        for (int p = 0; p < 4; ++p)
            #pragma unroll
            for (int j = 0; j < 4; ++j) acc[p][j] = 0ULL;

        #pragma unroll 8
        for (int k = 0; k < DIM; ++k) {
            float4 zv = *(const float4*)&zs[k][pt_t * 4];
            ull2   eA = *(const ull2*)&es[k][cg * 8];
            ull2   eB = *(const ull2*)&es[k][cg * 8 + 4];
            unsigned long long z0 = pk2(zv.x), z1 = pk2(zv.y);
            unsigned long long z2 = pk2(zv.z), z3 = pk2(zv.w);
            ffma2(acc[0][0], z0, eA.a); ffma2(acc[0][1], z0, eA.b);
            ffma2(acc[0][2], z0, eB.a); ffma2(acc[0][3], z0, eB.b);
            ffma2(acc[1][0], z1, eA.a); ffma2(acc[1][1], z1, eA.b);
            ffma2(acc[1][2], z1, eB.a); ffma2(acc[1][3], z1, eB.b);
            ffma2(acc[2][0], z2, eA.a); ffma2(acc[2][1], z2, eA.b);
            ffma2(acc[2][2], z2, eB.a); ffma2(acc[2][3], z2, eB.b);
            ffma2(acc[3][0], z3, eA.a); ffma2(acc[3][1], z3, eA.b);
            ffma2(acc[3][2], z3, eB.a); ffma2(acc[3][3], z3, eB.b);
        }

        __syncthreads();       // all warps done reading es before refill
        if (h + 1 < NH) {
            unsigned int dstn = (unsigned int)__cvta_generic_to_shared(&es[0][0]);
            #pragma unroll
            for (int i = 0; i < 8; ++i) {
                int f = i * 128 + tid;
                int k = f >> 4, c16 = f & 15;
                cpasync16(dstn + (unsigned)(k * HCH + c16 * 4) * 4u,
                          &d_est[(size_t)k * NE + c0 + (h + 1) * HCH + c16 * 4]);
            }
            CP_COMMIT();
        }

        // distances + running argmin (u64 key -> first-index tie-break)
        const int cbase = c0 + h * HCH + cg * 8;
        #pragma unroll
        for (int j = 0; j < 4; ++j) {
            float esq0 = __ldg(&d_esq[cbase + 2 * j]);
            float esq1 = __ldg(&d_esq[cbase + 2 * j + 1]);
            #pragma unroll
            for (int p = 0; p < 4; ++p) {
                float zq2 = zsq_s[pt_t * 4 + p];
                float2 dot = upk(acc[p][j]);
                {
                    float d = __fadd_rn(__fadd_rn(zq2, esq0), -2.0f * dot.x);
                    unsigned long long k64 =
                        ((unsigned long long)ordf(d) << 32) | (unsigned)(cbase + 2 * j);
                    if (k64 < best[p]) best[p] = k64;
                }
                {
                    float d = __fadd_rn(__fadd_rn(zq2, esq1), -2.0f * dot.y);
                    unsigned long long k64 =
                        ((unsigned long long)ordf(d) << 32) | (unsigned)(cbase + 2 * j + 1);
                    if (k64 < best[p]) best[p] = k64;
                }
            }
        }
    }

    // cross-thread argmin reduction within CTA, then merge across the 4 CTAs
    __syncthreads();
    #pragma unroll
    for (int p = 0; p < 4; ++p) red[cg][pt_t * 4 + p] = best[p];
    __syncthreads();

    if (tid < PTSB) {
        unsigned long long bk = red[0][tid];
        #pragma unroll
        for (int t = 1; t < 8; ++t) {
            unsigned long long v = red[t][tid];
            if (v < bk) bk = v;
        }
        atomicMin(&d_best[pt0 + tid], bk);
    }

    // tile ticket: 4th arriving CTA runs the epilogue
    __threadfence();
    __syncthreads();
    if (tid == 0) flag_s = (atomicAdd(&d_tile[tile], 1u) == NSPLIT - 1) ? 1 : 0;
    __syncthreads();
    if (!flag_s) return;

    if (tid < PTSB) {
        int n   = pt0 + tid;
        unsigned long long bk =
            *((volatile unsigned long long*)&d_best[n]);   // final (all fenced)
        int idx = (int)(unsigned int)bk;

        out[OFF_IDX + n] = (float)idx;
        atomicAdd(&d_count[idx], 1u);
        out[OFF_ENC + (unsigned long long)n * NE + (unsigned)idx] = 1.0f;

        // z_q gather + loss partial
        float errsum = 0.f;
        const float* er = emb + (size_t)idx * DIM;
        float* zq = out + OFF_ZQ + (size_t)b * BHW + hw0 + tid;
        #pragma unroll
        for (int c = 0; c < DIM; ++c) {
            float e  = __ldg(er + c);
            float zv = zs[c][tid];
            float df = e - zv;
            errsum   = fmaf(df, df, errsum);
            zq[(size_t)c * HW] = e;
        }
        #pragma unroll
        for (int o = 16; o > 0; o >>= 1)
            errsum += __shfl_down_sync(0xFFFFFFFFu, errsum, o);
        if ((tid & 31) == 0) atomicAdd(&d_loss, errsum);
    }

    // global ticket: last epilogue CTA computes perplexity + loss scalars
    __threadfence();
    __syncthreads();
    if (tid == 0) flag_s = (atomicAdd(&d_done, 1u) == NTILE - 1) ? 1 : 0;
    __syncthreads();
    if (flag_s) {
        float part = 0.f;
        #pragma unroll
        for (int i = 0; i < 8; ++i) {
            int c = tid + i * 128;
            float em = (float)*((volatile unsigned int*)&d_count[c])
                       * (1.0f / 32768.0f);
            part += em * logf(em + 1e-10f);
        }
        #pragma unroll
        for (int o = 16; o > 0; o >>= 1)
            part += __shfl_down_sync(0xFFFFFFFFu, part, o);
        if ((tid & 31) == 0) warp_s[tid >> 5] = part;
        __syncthreads();
        if (tid == 0) {
            float w = warp_s[0] + warp_s[1] + warp_s[2] + warp_s[3];
            out[OFF_PERP] = expf(-w);
            out[OFF_LOSS] = 1.25f * (*((volatile float*)&d_loss))
                            * (1.0f / 2097152.0f);
        }
    }
}

// ---------------------------------------------------------------- launch
extern "C" void kernel_launch(void* const* d_in, const int* in_sizes, int n_in,
                              void* d_out, int out_size) {
    const float* z   = (const float*)d_in[0];
    const float* emb = (const float*)d_in[1];
    float*       out = (float*)d_out;

    prep_kernel<<<32, 128>>>(emb);
    vq_main_kernel<<<NBLK, 128>>>(z, emb, out);
}

// round 15
// speedup vs baseline: 1.1577x; 1.0090x over previous
#include <cuda_runtime.h>
#include <cstdint>

// Problem constants
#define NPTS   32768            // 32 * 32 * 32 points
#define DIM    64               // embedding dim
#define NE     1024             // codebook size
#define HW     1024             // 32*32 spatial
#define BHW    65536            // 64 channels * 1024 hw (per-batch stride in z)
#define PTSB   64               // points per tile
#define CCH    128              // codes per CTA (one chunk, no refill)
#define NTILE  (NPTS / PTSB)    // 512 point tiles
#define NSPLIT 8                // code-split CTAs per tile
#define NBLK   (NTILE * NSPLIT) // 4096 CTAs

// Output layout (flat concat of reference return tuple, float32):
// loss[1], z_q[2097152], perplexity[1], min_encodings[33554432], indices[32768]
#define OFF_LOSS 0ULL
#define OFF_ZQ   1ULL
#define OFF_PERP 2097153ULL
#define OFF_ENC  2097154ULL
#define OFF_IDX  35651586ULL

__device__ float              d_esq[NE];
__device__ float              d_est[DIM * NE];   // transposed codebook [k][c]
__device__ float              d_zsq[NPTS];       // precomputed ||z||^2
__device__ unsigned int       d_count[NE];
__device__ unsigned long long d_best[NPTS];      // argmin keys (atomicMin merge)
__device__ unsigned int       d_tile[NTILE];     // per-tile arrival tickets
__device__ float              d_loss;
__device__ unsigned int       d_done;

// ---------------------------------------------------------------- helpers
struct __align__(16) ull2 { unsigned long long a, b; };

static __device__ __forceinline__ unsigned long long pk2(float v) {
    unsigned long long r;
    asm("mov.b64 %0, {%1,%2};" : "=l"(r) : "f"(v), "f"(v));
    return r;
}
static __device__ __forceinline__ void ffma2(unsigned long long& d,
                                             unsigned long long a,
                                             unsigned long long b) {
    asm("fma.rn.f32x2 %0, %1, %2, %0;" : "+l"(d) : "l"(a), "l"(b));
}
static __device__ __forceinline__ float2 upk(unsigned long long v) {
    float2 f;
    asm("mov.b64 {%0,%1}, %2;" : "=f"(f.x), "=f"(f.y) : "l"(v));
    return f;
}
static __device__ __forceinline__ unsigned int ordf(float x) {
    unsigned int b = __float_as_uint(x);
    return b ^ (unsigned int)(((int)b >> 31) | 0x80000000);
}
static __device__ __forceinline__ void cpasync16(unsigned int dst_smem,
                                                 const void* src) {
    asm volatile("cp.async.ca.shared.global [%0], [%1], 16;"
                 :: "r"(dst_smem), "l"(src));
}
#define CP_COMMIT() asm volatile("cp.async.commit_group;" ::: "memory")
#define CP_WAIT0()  asm volatile("cp.async.wait_group 0;" ::: "memory")

// ---------------------------------------------------------------- prep
// 32 blocks x 128 threads. Blocks 0-15: codebook transpose + ||e||^2 + counters.
// All blocks: re-init d_best / d_tile (graph-replay safe).
__global__ void prep_kernel(const float* __restrict__ emb) {
    __shared__ float sb[64][DIM + 1];
    const int tid = threadIdx.x;
    const int bid = blockIdx.x;
    const int g   = bid * 128 + tid;

    #pragma unroll
    for (int i = 0; i < 8; ++i) d_best[g + i * 4096] = 0xFFFFFFFFFFFFFFFFULL;
    if (g < NTILE) d_tile[g] = 0u;
    if (g == 0) { d_loss = 0.f; d_done = 0u; }

    if (bid < 16) {
        const int c0 = bid * 64;
        const float4* src = (const float4*)(emb + (size_t)c0 * DIM);
        #pragma unroll
        for (int i = 0; i < 8; ++i) {
            int f  = i * 128 + tid;
            int c  = f >> 4;
            int k4 = f & 15;
            float4 v = src[f];
            sb[c][k4 * 4 + 0] = v.x;
            sb[c][k4 * 4 + 1] = v.y;
            sb[c][k4 * 4 + 2] = v.z;
            sb[c][k4 * 4 + 3] = v.w;
        }
        __syncthreads();

        if (tid < 64) {
            const int c = c0 + tid;
            float s = 0.f;
            #pragma unroll
            for (int k = 0; k < DIM; ++k) {
                float v = sb[tid][k];
                s = __fadd_rn(s, __fmul_rn(v, v));
                d_est[k * NE + c] = v;
            }
            d_esq[c]   = s;
            d_count[c] = 0u;
        }
    }
}

// ---------------------------------------------------------------- zsq
// 256 blocks x 128 threads; per-point ||z||^2, sequential fp32 rn
// (identical rounding order to the reference-matching kernels).
// Consecutive threads read consecutive hw -> coalesced per k.
__global__ void zsq_kernel(const float* __restrict__ z) {
    const int n  = blockIdx.x * 128 + threadIdx.x;
    const int b  = n >> 10;
    const int hw = n & 1023;
    const float* p = z + (size_t)b * BHW + hw;
    float s = 0.f;
    #pragma unroll
    for (int k = 0; k < DIM; ++k) {
        float v = p[(size_t)k * HW];
        s = __fadd_rn(s, __fmul_rn(v, v));
    }
    d_zsq[n] = s;
}

// ---------------------------------------------------------------- main fused kernel
// CTA = (tile, octant): 64 points x 128 codes, ONE es chunk (no refill).
// 128 threads = 8 pt-groups (pt_t, 8 pts) x 16 code-groups (cg, 8 codes)
// thread tile: 8 points (4 NATURAL f32x2 pairs) x 8 codes (pk2-dup es)
//   per warp-k: 2 LDS.128 z (8 wf) + 8 broadcast LDS.32 es (8 wf)
//   = 16 wf vs 16 fma-cyc (32 ffma2)  ->  L1:fma = 1:1
//   acc[4][8] u64 = 64 regs.
__global__ void __launch_bounds__(128, 4)
vq_main_kernel(const float* __restrict__ z, const float* __restrict__ emb,
               float* __restrict__ out)
{
    __shared__ __align__(16) float zs[DIM][PTSB];      // [k][pt] 16 KB
    __shared__ __align__(16) float es[DIM][CCH];       // [k][c] 32 KB
    __shared__ float zsq_s[PTSB];
    __shared__ float warp_s[4];
    __shared__ int   flag_s;
    // red overlays es (only used after all FMAs): 16 x 64 x 8B = 8 KB
    unsigned long long (*red)[PTSB] = (unsigned long long (*)[PTSB])&es[0][0];

    const int tid  = threadIdx.x;
    const int pt_t = tid & 7;     // 0..7  point group (8 pts)
    const int cg   = tid >> 3;    // 0..15 code group (8 codes)
    const int tile = blockIdx.x >> 3;
    const int oct  = blockIdx.x & 7;          // code octant
    const int c0   = oct * CCH;
    const int pt0  = tile * PTSB;
    const int b    = pt0 >> 10;
    const int hw0  = pt0 & 1023;
    const float* zb = z + (size_t)b * BHW + hw0;

    // issue the single es chunk fetch immediately (32 KB from d_est)
    {
        unsigned int dst0 = (unsigned int)__cvta_generic_to_shared(&es[0][0]);
        #pragma unroll
        for (int i = 0; i < 16; ++i) {
            int f = i * 128 + tid;           // 16B unit 0..2047
            int k = f >> 5, c16 = f & 31;    // 32 units per k-row
            cpasync16(dst0 + (unsigned)(k * CCH + c16 * 4) * 4u,
                      &d_est[(size_t)k * NE + c0 + c16 * 4]);
        }
        CP_COMMIT();
    }

    // load z tile (coalesced), natural layout [k][pt]
    #pragma unroll
    for (int i = 0; i < 32; ++i) {
        int f = i * 128 + tid;
        int k = f >> 6, p = f & 63;
        zs[k][p] = zb[(size_t)k * HW + p];
    }

    // precomputed ||z||^2
    if (tid < PTSB) zsq_s[tid] = d_zsq[pt0 + tid];

    // one-hot zero-fill: this CTA covers its 1/8 of the tile's 65536 floats
    // (base%4==2 -> float4 body at +2, 16383 elements, plus head/tail scalars)
    {
        float* encb = out + OFF_ENC + (size_t)pt0 * NE;
        float4* e4  = (float4*)(encb + 2);
        if (tid == 0) {
            if (oct == 0) { encb[0] = 0.f; encb[1] = 0.f; }
            if (oct == 7) { encb[65534] = 0.f; encb[65535] = 0.f; }
        }
        #pragma unroll
        for (int i = 0; i < 16; ++i) {
            int j = oct * 2048 + i * 128 + tid;
            if (j < 16383) e4[j] = make_float4(0.f, 0.f, 0.f, 0.f);
        }
    }

    CP_WAIT0();
    __syncthreads();           // es + zs + zsq_s visible

    unsigned long long best[8];   // local point lp = pp*2 + (0|1)
    #pragma unroll
    for (int p = 0; p < 8; ++p) best[p] = 0xFFFFFFFFFFFFFFFFULL;

    unsigned long long acc[4][8];      // [point-pair][code]
    #pragma unroll
    for (int pp = 0; pp < 4; ++pp)
        #pragma unroll
        for (int j = 0; j < 8; ++j) acc[pp][j] = 0ULL;

    #pragma unroll 8
    for (int k = 0; k < DIM; ++k) {
        // 4 natural point-pairs: points pt_t*4..+3 and 32+pt_t*4..+3
        ull2 zA = *(const ull2*)&zs[k][pt_t * 4];        // pairs 0,1
        ull2 zB = *(const ull2*)&zs[k][32 + pt_t * 4];   // pairs 2,3
        const float* ek = &es[k][cg * 8];
        #pragma unroll
        for (int j = 0; j < 8; ++j) {
            unsigned long long ed = pk2(ek[j]);          // {e,e}
            ffma2(acc[0][j], zA.a, ed);
            ffma2(acc[1][j], zA.b, ed);
            ffma2(acc[2][j], zB.a, ed);
            ffma2(acc[3][j], zB.b, ed);
        }
    }

    // distances + running argmin (u64 key -> first-index tie-break)
    const int cbase = c0 + cg * 8;
    #pragma unroll
    for (int j = 0; j < 8; ++j) {
        float esq = __ldg(&d_esq[cbase + j]);
        unsigned code = (unsigned)(cbase + j);
        #pragma unroll
        for (int pp = 0; pp < 4; ++pp) {
            int pbase = (pp >> 1) * 32 + pt_t * 4 + (pp & 1) * 2;
            float2 dot = upk(acc[pp][j]);
            {
                float zq2 = zsq_s[pbase];
                float d = __fadd_rn(__fadd_rn(zq2, esq), -2.0f * dot.x);
                unsigned long long k64 =
                    ((unsigned long long)ordf(d) << 32) | code;
                if (k64 < best[pp * 2]) best[pp * 2] = k64;
            }
            {
                float zq2 = zsq_s[pbase + 1];
                float d = __fadd_rn(__fadd_rn(zq2, esq), -2.0f * dot.y);
                unsigned long long k64 =
                    ((unsigned long long)ordf(d) << 32) | code;
                if (k64 < best[pp * 2 + 1]) best[pp * 2 + 1] = k64;
            }
        }
    }

    // cross-thread argmin reduction within CTA (red overlays es)
    __syncthreads();
    #pragma unroll
    for (int pp = 0; pp < 4; ++pp) {
        int pbase = (pp >> 1) * 32 + pt_t * 4 + (pp & 1) * 2;
        red[cg][pbase]     = best[pp * 2];
        red[cg][pbase + 1] = best[pp * 2 + 1];
    }
    __syncthreads();

    if (tid < PTSB) {
        unsigned long long bk = red[0][tid];
        #pragma unroll
        for (int t = 1; t < 16; ++t) {
            unsigned long long v = red[t][tid];
            if (v < bk) bk = v;
        }
        atomicMin(&d_best[pt0 + tid], bk);
    }

    // tile ticket: 8th arriving CTA runs the epilogue
    __threadfence();
    __syncthreads();
    if (tid == 0) flag_s = (atomicAdd(&d_tile[tile], 1u) == NSPLIT - 1) ? 1 : 0;
    __syncthreads();
    if (!flag_s) return;

    if (tid < PTSB) {
        int n   = pt0 + tid;
        unsigned long long bk =
            *((volatile unsigned long long*)&d_best[n]);   // final (all fenced)
        int idx = (int)(unsigned int)bk;

        out[OFF_IDX + n] = (float)idx;
        atomicAdd(&d_count[idx], 1u);
        out[OFF_ENC + (unsigned long long)n * NE + (unsigned)idx] = 1.0f;

        // z_q gather + loss partial (straight-through: z_q_out == z_q in value)
        float errsum = 0.f;
        const float* er = emb + (size_t)idx * DIM;
        float* zq = out + OFF_ZQ + (size_t)b * BHW + hw0 + tid;
        #pragma unroll
        for (int c = 0; c < DIM; ++c) {
            float e  = __ldg(er + c);
            float zv = zs[c][tid];
            float df = e - zv;
            errsum   = fmaf(df, df, errsum);
            zq[(size_t)c * HW] = e;
        }
        #pragma unroll
        for (int o = 16; o > 0; o >>= 1)
            errsum += __shfl_down_sync(0xFFFFFFFFu, errsum, o);
        if ((tid & 31) == 0) atomicAdd(&d_loss, errsum);
    }

    // global ticket: last epilogue CTA computes perplexity + loss scalars
    __threadfence();
    __syncthreads();
    if (tid == 0) flag_s = (atomicAdd(&d_done, 1u) == NTILE - 1) ? 1 : 0;
    __syncthreads();
    if (flag_s) {
        float part = 0.f;
        #pragma unroll
        for (int i = 0; i < 8; ++i) {
            int c = tid + i * 128;
            float em = (float)*((volatile unsigned int*)&d_count[c])
                       * (1.0f / 32768.0f);
            part += em * logf(em + 1e-10f);
        }
        #pragma unroll
        for (int o = 16; o > 0; o >>= 1)
            part += __shfl_down_sync(0xFFFFFFFFu, part, o);
        if ((tid & 31) == 0) warp_s[tid >> 5] = part;
        __syncthreads();
        if (tid == 0) {
            float w = warp_s[0] + warp_s[1] + warp_s[2] + warp_s[3];
            out[OFF_PERP] = expf(-w);
            out[OFF_LOSS] = 1.25f * (*((volatile float*)&d_loss))
                            * (1.0f / 2097152.0f);
        }
    }
}

// ---------------------------------------------------------------- launch
extern "C" void kernel_launch(void* const* d_in, const int* in_sizes, int n_in,
                              void* d_out, int out_size) {
    const float* z   = (const float*)d_in[0];
    const float* emb = (const float*)d_in[1];
    float*       out = (float*)d_out;

    prep_kernel<<<32, 128>>>(emb);
    zsq_kernel<<<NPTS / 128, 128>>>(z);
    vq_main_kernel<<<NBLK, 128>>>(z, emb, out);
}